// round 5
// baseline (speedup 1.0000x reference)
#include <cuda_runtime.h>
#include <cuda_fp16.h>
#include <math.h>

#define H 128
#define CDIM 40
#define TMPW 64   /* padded half-row stride for layer-3 gather (128B) */
#define MAXN 100000

// scratch (device globals: allocation-free rule)
__device__ __align__(16) float  g_agg[(size_t)MAXN * H];     // 51.2 MB (f32 spmm out / gemm in)
__device__ __align__(16) __half g_xh [(size_t)MAXN * H];     // 25.6 MB
__device__ __align__(16) __half g_hb [(size_t)MAXN * H];     // 25.6 MB
__device__ __align__(16) __half g_tmp[(size_t)MAXN * TMPW];  // 12.8 MB
__device__ int g_rowptr[MAXN + 1];

// row_ptr[i] = lower_bound(dst, E, i); dst is sorted.
__global__ void rowptr_kernel(const int* __restrict__ dst, int E, int N,
                              int* __restrict__ rp) {
    int i = blockIdx.x * blockDim.x + threadIdx.x;
    if (i > N) return;
    int lo = 0, hi = E;
    while (lo < hi) {
        int m = (lo + hi) >> 1;
        if (dst[m] < i) lo = m + 1; else hi = m;
    }
    rp[i] = lo;
}

// f32 -> f16 convert (for layer-1 input x)
__global__ void f2h_kernel(const float* __restrict__ in, __half* __restrict__ out, int n2) {
    int i = blockIdx.x * blockDim.x + threadIdx.x;
    if (i < n2) {
        float2 v = ((const float2*)in)[i];
        ((__half2*)out)[i] = __floats2half2_rn(v.x, v.y);
    }
}

// Warp-per-row SPMM, fp16 payload, f32 accumulate. 128 features:
// 32 lanes x uint2 (4 halves) = 256B/edge = 2 L1 wavefronts.
__global__ __launch_bounds__(256) void spmm_h128(const __half* __restrict__ hin,
                                                 const int* __restrict__ src,
                                                 const float* __restrict__ w,
                                                 const int* __restrict__ rp,
                                                 float* __restrict__ out, int N) {
    const int lane = threadIdx.x & 31;
    const int r = blockIdx.x * 8 + (threadIdx.x >> 5);
    if (r >= N) return;
    const int e0 = rp[r];
    const int e1 = rp[r + 1];

    float4 acc = make_float4(0.f, 0.f, 0.f, 0.f);

    for (int e = e0; e < e1; e += 32) {
        const int idx = e + lane;
        const bool valid = idx < e1;
        const int   s  = valid ? src[idx] : 0;
        const float wv = valid ? w[idx]   : 0.f;
        const int cnt = e1 - e;

        #pragma unroll
        for (int g = 0; g < 4; ++g) {
            if (g * 8 < cnt) {
                int   sj[8]; float wj[8]; uint2 gv[8];
                #pragma unroll
                for (int j = 0; j < 8; ++j) {
                    sj[j] = __shfl_sync(0xffffffffu, s,  g * 8 + j);
                    wj[j] = __shfl_sync(0xffffffffu, wv, g * 8 + j);
                }
                #pragma unroll
                for (int j = 0; j < 8; ++j)   // 8 LDG.64 in flight
                    gv[j] = *(const uint2*)(hin + (size_t)sj[j] * H + lane * 4);
                #pragma unroll
                for (int j = 0; j < 8; ++j) {
                    const float2 f0 = __half22float2(*(const __half2*)&gv[j].x);
                    const float2 f1 = __half22float2(*(const __half2*)&gv[j].y);
                    acc.x += wj[j] * f0.x; acc.y += wj[j] * f0.y;
                    acc.z += wj[j] * f1.x; acc.w += wj[j] * f1.y;
                }
            }
        }
    }

    *(float4*)(out + (size_t)r * H + lane * 4) = acc;
}

// Layer-3 SPMM: fp16 payload (40 feats padded to 64-half rows = 128B),
// 20 active lanes x half2 = 1 L1 wavefront/edge. tanh fused; f32 output.
__global__ __launch_bounds__(256) void spmm_h40_tanh(const __half* __restrict__ hin,
                                                     const int* __restrict__ src,
                                                     const float* __restrict__ w,
                                                     const int* __restrict__ rp,
                                                     float* __restrict__ out, int N) {
    const int lane = threadIdx.x & 31;
    const int r = blockIdx.x * 8 + (threadIdx.x >> 5);
    if (r >= N) return;
    const int e0 = rp[r];
    const int e1 = rp[r + 1];

    float2 acc = make_float2(0.f, 0.f);

    for (int e = e0; e < e1; e += 32) {
        const int idx = e + lane;
        const bool valid = idx < e1;
        const int   s  = valid ? src[idx] : 0;
        const float wv = valid ? w[idx]   : 0.f;
        const int cnt = e1 - e;

        #pragma unroll
        for (int g = 0; g < 4; ++g) {
            if (g * 8 < cnt) {
                int sj[8]; float wj[8];
                #pragma unroll
                for (int j = 0; j < 8; ++j) {
                    sj[j] = __shfl_sync(0xffffffffu, s,  g * 8 + j);
                    wj[j] = __shfl_sync(0xffffffffu, wv, g * 8 + j);
                }
                __half2 gv[8];
                #pragma unroll
                for (int j = 0; j < 8; ++j)
                    gv[j] = (lane < 20) ? *(const __half2*)(hin + (size_t)sj[j] * TMPW + lane * 2)
                                        : __half2half2(__float2half(0.f));
                #pragma unroll
                for (int j = 0; j < 8; ++j) {
                    const float2 f = __half22float2(gv[j]);
                    acc.x += wj[j] * f.x; acc.y += wj[j] * f.y;
                }
            }
        }
    }

    if (lane < 20) {
        float2 o = make_float2(tanhf(acc.x), tanhf(acc.y));
        *(float2*)(out + (size_t)r * CDIM + lane * 2) = o;
    }
}

// C[N,128](half) = tanh(A[N,128](f32) @ W[128,128](f32)).
// BM=64, BN=128, BK=32, 256 threads, 4x8 tile (4x4 f32x2 acc).
// A tile row-major (pad 36): conflict-free STS, broadcast LDS.
#define SAPAD 36
__global__ __launch_bounds__(256, 3) void gemm128_tanh_h(const float* __restrict__ A,
                                                         const float* __restrict__ W,
                                                         __half* __restrict__ C, int N) {
    __shared__ float sA[64][SAPAD];   // [row][k]
    __shared__ float sW[32][128];     // [k][col]
    const int tid = threadIdx.x;
    const int tr = tid >> 4;          // 0..15 -> rows tr*4..tr*4+3
    const int tc = tid & 15;          // 0..15 -> cols tc*8..tc*8+7
    const int rowBase = blockIdx.x * 64;

    unsigned long long acc2[4][4];
    #pragma unroll
    for (int i = 0; i < 4; ++i)
        #pragma unroll
        for (int j = 0; j < 4; ++j) acc2[i][j] = 0ull;

    for (int kb = 0; kb < 128; kb += 32) {
        // A tile: 64 rows x 32 k, row-major. 2 float4 per thread.
        #pragma unroll
        for (int p = 0; p < 2; ++p) {
            int r = p * 32 + (tid >> 3);
            int c = (tid & 7) * 4;
            int gr = rowBase + r;
            float4 v = make_float4(0.f, 0.f, 0.f, 0.f);
            if (gr < N) v = *(const float4*)(A + (size_t)gr * 128 + kb + c);
            *(float4*)&sA[r][c] = v;
        }
        // W tile: 32 k x 128 cols. 4 float4 per thread.
        #pragma unroll
        for (int p = 0; p < 4; ++p) {
            int r = p * 8 + (tid >> 5);
            int c = (tid & 31) * 4;
            *(float4*)&sW[r][c] = *(const float4*)(W + (size_t)(kb + r) * 128 + c);
        }
        __syncthreads();

        #pragma unroll
        for (int k = 0; k < 32; ++k) {
            float a[4];
            unsigned long long b2[4];
            #pragma unroll
            for (int i = 0; i < 4; ++i) a[i] = sA[tr * 4 + i][k];   // 2-addr broadcast
            *(float4*)(&b2[0]) = *(const float4*)&sW[k][tc * 8];
            *(float4*)(&b2[2]) = *(const float4*)&sW[k][tc * 8 + 4];
            #pragma unroll
            for (int i = 0; i < 4; ++i) {
                unsigned long long a2;
                asm("mov.b64 %0, {%1, %1};" : "=l"(a2) : "f"(a[i]));
                #pragma unroll
                for (int j = 0; j < 4; ++j)
                    asm("fma.rn.f32x2 %0, %1, %2, %0;"
                        : "+l"(acc2[i][j]) : "l"(a2), "l"(b2[j]));
            }
        }
        __syncthreads();
    }

    #pragma unroll
    for (int i = 0; i < 4; ++i) {
        int gr = rowBase + tr * 4 + i;
        if (gr < N) {
            uint4 o;
            #pragma unroll
            for (int j = 0; j < 4; ++j) {
                float2 p = *(float2*)&acc2[i][j];
                __half2 h = __floats2half2_rn(tanhf(p.x), tanhf(p.y));
                ((unsigned*)&o)[j] = *(unsigned*)&h;
            }
            *(uint4*)(C + (size_t)gr * 128 + tc * 8) = o;
        }
    }
}

// tmp[N, pad64](half) = A[N,128](half) @ W2[128,40](f32)
__global__ __launch_bounds__(160) void gemm40_h(const __half* __restrict__ A,
                                                const float* __restrict__ W2,
                                                __half* __restrict__ out, int N) {
    __shared__ float sW2[128 * 40];
    __shared__ float sAr[16][128];
    const int t = threadIdx.x;
    const int tx = t % 40;
    const int ty = t / 40;
    const int rowBase = blockIdx.x * 16;

    for (int i = t; i < 128 * 40; i += 160) sW2[i] = W2[i];
    for (int i = t; i < 16 * 64; i += 160) {   // 16 rows x 64 half2
        int r = i >> 6, c = (i & 63) * 2;
        int gr = rowBase + r;
        float2 v = make_float2(0.f, 0.f);
        if (gr < N) v = __half22float2(*(const __half2*)(A + (size_t)gr * 128 + c));
        sAr[r][c] = v.x; sAr[r][c + 1] = v.y;
    }
    __syncthreads();

    float acc[4] = {0.f, 0.f, 0.f, 0.f};
    #pragma unroll 8
    for (int k = 0; k < 128; ++k) {
        float wv = sW2[k * 40 + tx];
        #pragma unroll
        for (int r = 0; r < 4; ++r)
            acc[r] += sAr[ty * 4 + r][k] * wv;
    }
    #pragma unroll
    for (int r = 0; r < 4; ++r) {
        int gr = rowBase + ty * 4 + r;
        if (gr < N) out[(size_t)gr * TMPW + tx] = __float2half(acc[r]);
    }
}

extern "C" void kernel_launch(void* const* d_in, const int* in_sizes, int n_in,
                              void* d_out, int out_size) {
    const float* x    = (const float*)d_in[0];
    const int*   esrc = (const int*)d_in[1];
    const int*   edst = (const int*)d_in[2];
    const float* ew   = (const float*)d_in[3];
    const float* W0   = (const float*)d_in[4];
    const float* W1   = (const float*)d_in[5];
    const float* W2   = (const float*)d_in[6];
    float* out = (float*)d_out;

    const int N = in_sizes[0] / H;
    const int E = in_sizes[1];

    float* agg; __half *xh, *hb, *tmp; int* rp;
    cudaGetSymbolAddress((void**)&agg, g_agg);
    cudaGetSymbolAddress((void**)&xh,  g_xh);
    cudaGetSymbolAddress((void**)&hb,  g_hb);
    cudaGetSymbolAddress((void**)&tmp, g_tmp);
    cudaGetSymbolAddress((void**)&rp,  g_rowptr);

    const int gemmBlocks = (N + 63) / 64;
    const int spmmBlocks = (N + 7) / 8;

    rowptr_kernel<<<(N + 256) / 256, 256>>>(edst, E, N, rp);
    f2h_kernel<<<(N * H / 2 + 255) / 256, 256>>>(x, xh, N * H / 2);

    // layer 1: h = tanh(spmm(x) @ W0)
    spmm_h128<<<spmmBlocks, 256>>>(xh, esrc, ew, rp, agg, N);
    gemm128_tanh_h<<<gemmBlocks, 256>>>(agg, W0, hb, N);

    // layer 2: h = tanh(spmm(h) @ W1)
    spmm_h128<<<spmmBlocks, 256>>>(hb, esrc, ew, rp, agg, N);
    gemm128_tanh_h<<<gemmBlocks, 256>>>(agg, W1, hb, N);

    // layer 3 (reassociated): out = tanh(spmm(h @ W2)) -- 40-wide fp16 gather
    gemm40_h<<<(N + 15) / 16, 160>>>(hb, W2, tmp, N);
    spmm_h40_tanh<<<spmmBlocks, 256>>>(tmp, esrc, ew, rp, out, N);
}

// round 6
// speedup vs baseline: 1.3561x; 1.3561x over previous
#include <cuda_runtime.h>
#include <cuda_fp16.h>
#include <math.h>

#define H 128
#define CDIM 40
#define TMPW 64   /* padded half-row stride for layer-3 gather (128B) */
#define MAXN 100000
#define KP 40     /* padded k-stride (halves) for mma smem tiles: conflict-free */

// scratch (device globals: allocation-free rule)
__device__ __align__(16) float  g_agg[(size_t)MAXN * H];     // 51.2 MB
__device__ __align__(16) __half g_xh [(size_t)MAXN * H];     // 25.6 MB
__device__ __align__(16) __half g_hb [(size_t)MAXN * H];     // 25.6 MB
__device__ __align__(16) __half g_tmp[(size_t)MAXN * TMPW];  // 12.8 MB
__device__ int g_rowptr[MAXN + 1];
// pre-split, pre-transposed weights: WT[n][k], hi/lo fp16 halves of f32
__device__ __align__(16) __half g_W0T_hi[H * H], g_W0T_lo[H * H];
__device__ __align__(16) __half g_W1T_hi[H * H], g_W1T_lo[H * H];

// row_ptr[i] = lower_bound(dst, E, i); dst is sorted.
__global__ void rowptr_kernel(const int* __restrict__ dst, int E, int N,
                              int* __restrict__ rp) {
    int i = blockIdx.x * blockDim.x + threadIdx.x;
    if (i > N) return;
    int lo = 0, hi = E;
    while (lo < hi) {
        int m = (lo + hi) >> 1;
        if (dst[m] < i) lo = m + 1; else hi = m;
    }
    rp[i] = lo;
}

// f32 -> f16 convert (for layer-1 input x)
__global__ void f2h_kernel(const float* __restrict__ in, __half* __restrict__ out, int n2) {
    int i = blockIdx.x * blockDim.x + threadIdx.x;
    if (i < n2) {
        float2 v = ((const float2*)in)[i];
        ((__half2*)out)[i] = __floats2half2_rn(v.x, v.y);
    }
}

// W[k][n] f32 -> WT_hi/WT_lo[n][k] fp16 split (hi + lo ~= exact f32)
__global__ void wsplit_kernel(const float* __restrict__ W,
                              __half* __restrict__ Thi, __half* __restrict__ Tlo) {
    int i = blockIdx.x * blockDim.x + threadIdx.x;
    if (i >= H * H) return;
    int k = i >> 7, n = i & 127;
    float v = W[k * H + n];
    __half hi = __float2half_rn(v);
    float lo = v - __half2float(hi);
    Thi[n * H + k] = hi;
    Tlo[n * H + k] = __float2half_rn(lo);
}

// Warp-per-row SPMM, fp16 payload, f32 accumulate (round-4 verbatim).
__global__ __launch_bounds__(256) void spmm_h128(const __half* __restrict__ hin,
                                                 const int* __restrict__ src,
                                                 const float* __restrict__ w,
                                                 const int* __restrict__ rp,
                                                 float* __restrict__ out, int N) {
    const int lane = threadIdx.x & 31;
    const int r = blockIdx.x * 8 + (threadIdx.x >> 5);
    if (r >= N) return;
    const int e0 = rp[r];
    const int e1 = rp[r + 1];

    float4 acc = make_float4(0.f, 0.f, 0.f, 0.f);

    for (int e = e0; e < e1; e += 32) {
        const int idx = e + lane;
        const bool valid = idx < e1;
        const int   s  = valid ? src[idx] : 0;
        const float wv = valid ? w[idx]   : 0.f;
        const int cnt = e1 - e;

        #pragma unroll
        for (int g = 0; g < 4; ++g) {
            if (g * 8 < cnt) {
                #pragma unroll
                for (int j = 0; j < 8; ++j) {
                    const int   sj = __shfl_sync(0xffffffffu, s,  g * 8 + j);
                    const float wj = __shfl_sync(0xffffffffu, wv, g * 8 + j);
                    const uint2 gv = *(const uint2*)(hin + (size_t)sj * H + lane * 4);
                    const float2 f0 = __half22float2(*(const __half2*)&gv.x);
                    const float2 f1 = __half22float2(*(const __half2*)&gv.y);
                    acc.x += wj * f0.x; acc.y += wj * f0.y;
                    acc.z += wj * f1.x; acc.w += wj * f1.y;
                }
            }
        }
    }

    *(float4*)(out + (size_t)r * H + lane * 4) = acc;
}

// Layer-3 SPMM (round-4 verbatim): 40 feats padded to 64-half rows, tanh fused.
__global__ __launch_bounds__(256) void spmm_h40_tanh(const __half* __restrict__ hin,
                                                     const int* __restrict__ src,
                                                     const float* __restrict__ w,
                                                     const int* __restrict__ rp,
                                                     float* __restrict__ out, int N) {
    const int lane = threadIdx.x & 31;
    const int r = blockIdx.x * 8 + (threadIdx.x >> 5);
    if (r >= N) return;
    const int e0 = rp[r];
    const int e1 = rp[r + 1];

    float2 acc = make_float2(0.f, 0.f);

    for (int e = e0; e < e1; e += 32) {
        const int idx = e + lane;
        const bool valid = idx < e1;
        const int   s  = valid ? src[idx] : 0;
        const float wv = valid ? w[idx]   : 0.f;
        const int cnt = e1 - e;

        #pragma unroll
        for (int g = 0; g < 4; ++g) {
            if (g * 8 < cnt) {
                #pragma unroll
                for (int j = 0; j < 8; ++j) {
                    const int   sj = __shfl_sync(0xffffffffu, s,  g * 8 + j);
                    const float wj = __shfl_sync(0xffffffffu, wv, g * 8 + j);
                    if (lane < 20) {
                        const __half2 gv = *(const __half2*)(hin + (size_t)sj * TMPW + lane * 2);
                        const float2 f = __half22float2(gv);
                        acc.x += wj * f.x; acc.y += wj * f.y;
                    }
                }
            }
        }
    }

    if (lane < 20) {
        float2 o = make_float2(tanhf(acc.x), tanhf(acc.y));
        *(float2*)(out + (size_t)r * CDIM + lane * 2) = o;
    }
}

#define MMA3(cacc, a, b0, b1)                                              \
    asm volatile("mma.sync.aligned.m16n8k16.row.col.f32.f16.f16.f32 "      \
                 "{%0,%1,%2,%3}, {%4,%5,%6,%7}, {%8,%9}, {%0,%1,%2,%3};"   \
                 : "+f"(cacc[0]), "+f"(cacc[1]), "+f"(cacc[2]), "+f"(cacc[3]) \
                 : "r"(a[0]), "r"(a[1]), "r"(a[2]), "r"(a[3]), "r"(b0), "r"(b1))

// C[N,128](half) = tanh(A[N,128](f32) @ W) via split-fp16 tensor-core MMA.
// Block: 256 thr (8 warps), BM=128, full N=128 cols, BK=32. Warp w: rows w*16..+15.
__global__ __launch_bounds__(256, 2) void gemm128_mma_tanh(const float* __restrict__ A,
                                                           const __half* __restrict__ WThi,
                                                           const __half* __restrict__ WTlo,
                                                           __half* __restrict__ C, int N) {
    __shared__ __half sAh[128][KP], sAl[128][KP];
    __shared__ __half sWh[128][KP], sWl[128][KP];
    const int tid = threadIdx.x;
    const int lane = tid & 31;
    const int w = tid >> 5;
    const int rowBase = blockIdx.x * 128;

    float acc[16][4];
    #pragma unroll
    for (int t = 0; t < 16; ++t)
        #pragma unroll
        for (int j = 0; j < 4; ++j) acc[t][j] = 0.f;

    for (int kb = 0; kb < 128; kb += 32) {
        __syncthreads();
        // A slice: 128 rows x 32 k -> split to hi/lo halves
        #pragma unroll
        for (int p = 0; p < 4; ++p) {
            int idx = p * 256 + tid;
            int r = idx >> 3, c = (idx & 7) * 4;
            int gr = rowBase + r;
            float4 v = make_float4(0.f, 0.f, 0.f, 0.f);
            if (gr < N) v = *(const float4*)(A + (size_t)gr * 128 + kb + c);
            __half h0 = __float2half_rn(v.x), h1 = __float2half_rn(v.y);
            __half h2 = __float2half_rn(v.z), h3 = __float2half_rn(v.w);
            __half l0 = __float2half_rn(v.x - __half2float(h0));
            __half l1 = __float2half_rn(v.y - __half2float(h1));
            __half l2 = __float2half_rn(v.z - __half2float(h2));
            __half l3 = __float2half_rn(v.w - __half2float(h3));
            *(__half2*)&sAh[r][c]     = __halves2half2(h0, h1);
            *(__half2*)&sAh[r][c + 2] = __halves2half2(h2, h3);
            *(__half2*)&sAl[r][c]     = __halves2half2(l0, l1);
            *(__half2*)&sAl[r][c + 2] = __halves2half2(l2, l3);
        }
        // W slices: WT[n][kb..kb+31] hi/lo, 16B vectors
        #pragma unroll
        for (int p = 0; p < 2; ++p) {
            int idx = p * 256 + tid;
            int n = idx >> 2, c = (idx & 3) * 8;
            *(uint4*)&sWh[n][c] = *(const uint4*)(WThi + n * 128 + kb + c);
            *(uint4*)&sWl[n][c] = *(const uint4*)(WTlo + n * 128 + kb + c);
        }
        __syncthreads();

        #pragma unroll
        for (int ks = 0; ks < 2; ++ks) {
            const int koff = ks * 16 + (lane & 3) * 2;
            const int ra = w * 16 + (lane >> 2);
            unsigned ah[4], al[4];
            ah[0] = *(const unsigned*)&sAh[ra][koff];
            ah[1] = *(const unsigned*)&sAh[ra + 8][koff];
            ah[2] = *(const unsigned*)&sAh[ra][koff + 8];
            ah[3] = *(const unsigned*)&sAh[ra + 8][koff + 8];
            al[0] = *(const unsigned*)&sAl[ra][koff];
            al[1] = *(const unsigned*)&sAl[ra + 8][koff];
            al[2] = *(const unsigned*)&sAl[ra][koff + 8];
            al[3] = *(const unsigned*)&sAl[ra + 8][koff + 8];
            #pragma unroll
            for (int nt = 0; nt < 16; ++nt) {
                const int nb = nt * 8 + (lane >> 2);
                unsigned bh0 = *(const unsigned*)&sWh[nb][koff];
                unsigned bh1 = *(const unsigned*)&sWh[nb][koff + 8];
                unsigned bl0 = *(const unsigned*)&sWl[nb][koff];
                unsigned bl1 = *(const unsigned*)&sWl[nb][koff + 8];
                MMA3(acc[nt], ah, bh0, bh1);   // hi*hi
                MMA3(acc[nt], ah, bl0, bl1);   // hi*lo
                MMA3(acc[nt], al, bh0, bh1);   // lo*hi  (lo*lo ~2^-22, dropped)
            }
        }
    }

    // epilogue: c0,c1 -> row g, cols 2t..2t+1 ; c2,c3 -> row g+8
    const int r0 = rowBase + w * 16 + (lane >> 2);
    const int colb = (lane & 3) * 2;
    #pragma unroll
    for (int nt = 0; nt < 16; ++nt) {
        if (r0 < N) {
            __half2 h = __floats2half2_rn(tanhf(acc[nt][0]), tanhf(acc[nt][1]));
            *(__half2*)(C + (size_t)r0 * 128 + nt * 8 + colb) = h;
        }
        if (r0 + 8 < N) {
            __half2 h = __floats2half2_rn(tanhf(acc[nt][2]), tanhf(acc[nt][3]));
            *(__half2*)(C + (size_t)(r0 + 8) * 128 + nt * 8 + colb) = h;
        }
    }
}

// tmp[N, pad64](half) = A[N,128](half) @ W2[128,40](f32)  (round-4 verbatim)
__global__ __launch_bounds__(160) void gemm40_h(const __half* __restrict__ A,
                                                const float* __restrict__ W2,
                                                __half* __restrict__ out, int N) {
    __shared__ float sW2[128 * 40];
    __shared__ float sAr[16][128];
    const int t = threadIdx.x;
    const int tx = t % 40;
    const int ty = t / 40;
    const int rowBase = blockIdx.x * 16;

    for (int i = t; i < 128 * 40; i += 160) sW2[i] = W2[i];
    for (int i = t; i < 16 * 64; i += 160) {
        int r = i >> 6, c = (i & 63) * 2;
        int gr = rowBase + r;
        float2 v = make_float2(0.f, 0.f);
        if (gr < N) v = __half22float2(*(const __half2*)(A + (size_t)gr * 128 + c));
        sAr[r][c] = v.x; sAr[r][c + 1] = v.y;
    }
    __syncthreads();

    float acc[4] = {0.f, 0.f, 0.f, 0.f};
    #pragma unroll 8
    for (int k = 0; k < 128; ++k) {
        float wv = sW2[k * 40 + tx];
        #pragma unroll
        for (int r = 0; r < 4; ++r)
            acc[r] += sAr[ty * 4 + r][k] * wv;
    }
    #pragma unroll
    for (int r = 0; r < 4; ++r) {
        int gr = rowBase + ty * 4 + r;
        if (gr < N) out[(size_t)gr * TMPW + tx] = __float2half(acc[r]);
    }
}

extern "C" void kernel_launch(void* const* d_in, const int* in_sizes, int n_in,
                              void* d_out, int out_size) {
    const float* x    = (const float*)d_in[0];
    const int*   esrc = (const int*)d_in[1];
    const int*   edst = (const int*)d_in[2];
    const float* ew   = (const float*)d_in[3];
    const float* W0   = (const float*)d_in[4];
    const float* W1   = (const float*)d_in[5];
    const float* W2   = (const float*)d_in[6];
    float* out = (float*)d_out;

    const int N = in_sizes[0] / H;
    const int E = in_sizes[1];

    float* agg; __half *xh, *hb, *tmp; int* rp;
    __half *w0h, *w0l, *w1h, *w1l;
    cudaGetSymbolAddress((void**)&agg, g_agg);
    cudaGetSymbolAddress((void**)&xh,  g_xh);
    cudaGetSymbolAddress((void**)&hb,  g_hb);
    cudaGetSymbolAddress((void**)&tmp, g_tmp);
    cudaGetSymbolAddress((void**)&rp,  g_rowptr);
    cudaGetSymbolAddress((void**)&w0h, g_W0T_hi);
    cudaGetSymbolAddress((void**)&w0l, g_W0T_lo);
    cudaGetSymbolAddress((void**)&w1h, g_W1T_hi);
    cudaGetSymbolAddress((void**)&w1l, g_W1T_lo);

    const int gemmBlocks = (N + 127) / 128;
    const int spmmBlocks = (N + 7) / 8;

    rowptr_kernel<<<(N + 256) / 256, 256>>>(edst, E, N, rp);
    f2h_kernel<<<(N * H / 2 + 255) / 256, 256>>>(x, xh, N * H / 2);
    wsplit_kernel<<<(H * H + 255) / 256, 256>>>(W0, w0h, w0l);
    wsplit_kernel<<<(H * H + 255) / 256, 256>>>(W1, w1h, w1l);

    // layer 1: h = tanh(spmm(x) @ W0)
    spmm_h128<<<spmmBlocks, 256>>>(xh, esrc, ew, rp, agg, N);
    gemm128_mma_tanh<<<gemmBlocks, 256>>>(agg, w0h, w0l, hb, N);

    // layer 2: h = tanh(spmm(h) @ W1)
    spmm_h128<<<spmmBlocks, 256>>>(hb, esrc, ew, rp, agg, N);
    gemm128_mma_tanh<<<gemmBlocks, 256>>>(agg, w1h, w1l, hb, N);

    // layer 3 (reassociated): out = tanh(spmm(h @ W2)) -- 40-wide fp16 gather
    gemm40_h<<<(N + 15) / 16, 160>>>(hb, W2, tmp, N);
    spmm_h40_tanh<<<spmmBlocks, 256>>>(tmp, esrc, ew, rp, out, N);
}

// round 11
// speedup vs baseline: 1.5596x; 1.1501x over previous
#include <cuda_runtime.h>
#include <cuda_fp16.h>
#include <math.h>

#define H 128
#define CDIM 40
#define TMPW 64   /* padded half-row stride for layer-3 gather (128B) */
#define MAXN 100000
#define KP 40     /* padded k-stride (halves) for 32-k mma smem tiles */
#define KP2 136   /* padded k-stride (halves) for full-K W2 tile */

// scratch (device globals: allocation-free rule)
__device__ __align__(16) float  g_agg[(size_t)MAXN * H];     // 51.2 MB
__device__ __align__(16) __half g_xh [(size_t)MAXN * H];     // 25.6 MB
__device__ __align__(16) __half g_hb [(size_t)MAXN * H];     // 25.6 MB
__device__ __align__(16) __half g_tmp[(size_t)MAXN * TMPW];  // 12.8 MB
__device__ int g_rowptr[MAXN + 1];
// pre-split, pre-transposed weights: WT[n][k] fp16 hi/lo halves of f32
__device__ __align__(16) __half g_W0T_hi[H * H], g_W0T_lo[H * H];
__device__ __align__(16) __half g_W1T_hi[H * H], g_W1T_lo[H * H];
__device__ __align__(16) __half g_W2T_hi[CDIM * H], g_W2T_lo[CDIM * H];

#define MMA(cacc, a, b0, b1)                                                 \
    asm volatile("mma.sync.aligned.m16n8k16.row.col.f32.f16.f16.f32 "        \
                 "{%0,%1,%2,%3}, {%4,%5,%6,%7}, {%8,%9}, {%0,%1,%2,%3};"     \
                 : "+f"(cacc[0]), "+f"(cacc[1]), "+f"(cacc[2]), "+f"(cacc[3])\
                 : "r"(a[0]), "r"(a[1]), "r"(a[2]), "r"(a[3]), "r"(b0), "r"(b1))

// ---------------- fused prep: f2h + rowptr + 3x weight split -----------------
__global__ void prep_kernel(const float* __restrict__ x, int n2h, int bF,
                            const int* __restrict__ dst, int E, int N, int bR,
                            const float* __restrict__ W0, const float* __restrict__ W1,
                            const float* __restrict__ W2, int bW,
                            __half* __restrict__ xh, int* __restrict__ rp) {
    const int b = blockIdx.x, t = threadIdx.x;
    if (b < bF) {                                  // f32 -> f16 convert of x
        int i = b * 256 + t;
        if (i < n2h) {
            float2 v = ((const float2*)x)[i];
            ((__half2*)xh)[i] = __floats2half2_rn(v.x, v.y);
        }
    } else if (b < bF + bR) {                      // row_ptr via lower_bound
        int i = (b - bF) * 256 + t;
        if (i <= N) {
            int lo = 0, hi = E;
            while (lo < hi) {
                int m = (lo + hi) >> 1;
                if (dst[m] < i) lo = m + 1; else hi = m;
            }
            rp[i] = lo;
        }
    } else if (b < bF + bR + 2 * bW) {             // W0 / W1 split+transpose
        int wi = b - bF - bR;
        const float* W = (wi < bW) ? W0 : W1;
        __half* Th = (wi < bW) ? g_W0T_hi : g_W1T_hi;
        __half* Tl = (wi < bW) ? g_W0T_lo : g_W1T_lo;
        int i = (wi % bW) * 256 + t;
        if (i < H * H) {
            int k = i >> 7, n = i & 127;
            float v = W[k * H + n];
            __half hi = __float2half_rn(v);
            Th[n * H + k] = hi;
            Tl[n * H + k] = __float2half_rn(v - __half2float(hi));
        }
    } else {                                       // W2 split+transpose [k<128][n<40]
        int i = (b - bF - bR - 2 * bW) * 256 + t;
        if (i < H * CDIM) {
            int k = i / CDIM, n = i % CDIM;
            float v = W2[k * CDIM + n];
            __half hi = __float2half_rn(v);
            g_W2T_hi[n * H + k] = hi;
            g_W2T_lo[n * H + k] = __float2half_rn(v - __half2float(hi));
        }
    }
}

// ---------------- SPMM kernels (round-4/6 verbatim, proven) ------------------
__global__ __launch_bounds__(256) void spmm_h128(const __half* __restrict__ hin,
                                                 const int* __restrict__ src,
                                                 const float* __restrict__ w,
                                                 const int* __restrict__ rp,
                                                 float* __restrict__ out, int N) {
    const int lane = threadIdx.x & 31;
    const int r = blockIdx.x * 8 + (threadIdx.x >> 5);
    if (r >= N) return;
    const int e0 = rp[r];
    const int e1 = rp[r + 1];

    float4 acc = make_float4(0.f, 0.f, 0.f, 0.f);

    for (int e = e0; e < e1; e += 32) {
        const int idx = e + lane;
        const bool valid = idx < e1;
        const int   s  = valid ? src[idx] : 0;
        const float wv = valid ? w[idx]   : 0.f;
        const int cnt = e1 - e;

        #pragma unroll
        for (int g = 0; g < 4; ++g) {
            if (g * 8 < cnt) {
                #pragma unroll
                for (int j = 0; j < 8; ++j) {
                    const int   sj = __shfl_sync(0xffffffffu, s,  g * 8 + j);
                    const float wj = __shfl_sync(0xffffffffu, wv, g * 8 + j);
                    const uint2 gv = *(const uint2*)(hin + (size_t)sj * H + lane * 4);
                    const float2 f0 = __half22float2(*(const __half2*)&gv.x);
                    const float2 f1 = __half22float2(*(const __half2*)&gv.y);
                    acc.x += wj * f0.x; acc.y += wj * f0.y;
                    acc.z += wj * f1.x; acc.w += wj * f1.y;
                }
            }
        }
    }

    *(float4*)(out + (size_t)r * H + lane * 4) = acc;
}

__global__ __launch_bounds__(256) void spmm_h40_tanh(const __half* __restrict__ hin,
                                                     const int* __restrict__ src,
                                                     const float* __restrict__ w,
                                                     const int* __restrict__ rp,
                                                     float* __restrict__ out, int N) {
    const int lane = threadIdx.x & 31;
    const int r = blockIdx.x * 8 + (threadIdx.x >> 5);
    if (r >= N) return;
    const int e0 = rp[r];
    const int e1 = rp[r + 1];

    float2 acc = make_float2(0.f, 0.f);

    for (int e = e0; e < e1; e += 32) {
        const int idx = e + lane;
        const bool valid = idx < e1;
        const int   s  = valid ? src[idx] : 0;
        const float wv = valid ? w[idx]   : 0.f;
        const int cnt = e1 - e;

        #pragma unroll
        for (int g = 0; g < 4; ++g) {
            if (g * 8 < cnt) {
                #pragma unroll
                for (int j = 0; j < 8; ++j) {
                    const int   sj = __shfl_sync(0xffffffffu, s,  g * 8 + j);
                    const float wj = __shfl_sync(0xffffffffu, wv, g * 8 + j);
                    if (lane < 20) {
                        const __half2 gv = *(const __half2*)(hin + (size_t)sj * TMPW + lane * 2);
                        const float2 f = __half22float2(gv);
                        acc.x += wj * f.x; acc.y += wj * f.y;
                    }
                }
            }
        }
    }

    if (lane < 20) {
        float2 o = make_float2(tanhf(acc.x), tanhf(acc.y));
        *(float2*)(out + (size_t)r * CDIM + lane * 2) = o;
    }
}

// ------ C[N,128](half) = tanh(A(f32) @ W) split-fp16 MMA (round-6 verbatim) --
__global__ __launch_bounds__(256, 2) void gemm128_mma_tanh(const float* __restrict__ A,
                                                           const __half* __restrict__ WThi,
                                                           const __half* __restrict__ WTlo,
                                                           __half* __restrict__ C, int N) {
    __shared__ __half sAh[128][KP], sAl[128][KP];
    __shared__ __half sWh[128][KP], sWl[128][KP];
    const int tid = threadIdx.x;
    const int lane = tid & 31;
    const int w = tid >> 5;
    const int rowBase = blockIdx.x * 128;

    float acc[16][4];
    #pragma unroll
    for (int t = 0; t < 16; ++t)
        #pragma unroll
        for (int j = 0; j < 4; ++j) acc[t][j] = 0.f;

    for (int kb = 0; kb < 128; kb += 32) {
        __syncthreads();
        // A slice: 128 rows x 32 k -> hi/lo split
        #pragma unroll
        for (int p = 0; p < 4; ++p) {
            int idx = p * 256 + tid;
            int r = idx >> 3, c = (idx & 7) * 4;
            int gr = rowBase + r;
            float4 v = make_float4(0.f, 0.f, 0.f, 0.f);
            if (gr < N) v = *(const float4*)(A + (size_t)gr * 128 + kb + c);
            __half h0 = __float2half_rn(v.x), h1 = __float2half_rn(v.y);
            __half h2 = __float2half_rn(v.z), h3 = __float2half_rn(v.w);
            __half l0 = __float2half_rn(v.x - __half2float(h0));
            __half l1 = __float2half_rn(v.y - __half2float(h1));
            __half l2 = __float2half_rn(v.z - __half2float(h2));
            __half l3 = __float2half_rn(v.w - __half2float(h3));
            *(__half2*)&sAh[r][c]     = __halves2half2(h0, h1);
            *(__half2*)&sAh[r][c + 2] = __halves2half2(h2, h3);
            *(__half2*)&sAl[r][c]     = __halves2half2(l0, l1);
            *(__half2*)&sAl[r][c + 2] = __halves2half2(l2, l3);
        }
        // W slices: WT[n][kb..kb+31]
        #pragma unroll
        for (int p = 0; p < 2; ++p) {
            int idx = p * 256 + tid;
            int n = idx >> 2, c = (idx & 3) * 8;
            *(uint4*)&sWh[n][c] = *(const uint4*)(WThi + n * 128 + kb + c);
            *(uint4*)&sWl[n][c] = *(const uint4*)(WTlo + n * 128 + kb + c);
        }
        __syncthreads();

        #pragma unroll
        for (int ks = 0; ks < 2; ++ks) {
            const int koff = ks * 16 + (lane & 3) * 2;
            const int ra = w * 16 + (lane >> 2);
            unsigned ah[4], al[4];
            ah[0] = *(const unsigned*)&sAh[ra][koff];
            ah[1] = *(const unsigned*)&sAh[ra + 8][koff];
            ah[2] = *(const unsigned*)&sAh[ra][koff + 8];
            ah[3] = *(const unsigned*)&sAh[ra + 8][koff + 8];
            al[0] = *(const unsigned*)&sAl[ra][koff];
            al[1] = *(const unsigned*)&sAl[ra + 8][koff];
            al[2] = *(const unsigned*)&sAl[ra][koff + 8];
            al[3] = *(const unsigned*)&sAl[ra + 8][koff + 8];
            #pragma unroll
            for (int nt = 0; nt < 16; ++nt) {
                const int nb = nt * 8 + (lane >> 2);
                unsigned bh0 = *(const unsigned*)&sWh[nb][koff];
                unsigned bh1 = *(const unsigned*)&sWh[nb][koff + 8];
                unsigned bl0 = *(const unsigned*)&sWl[nb][koff];
                unsigned bl1 = *(const unsigned*)&sWl[nb][koff + 8];
                MMA(acc[nt], ah, bh0, bh1);   // hi*hi
                MMA(acc[nt], ah, bl0, bl1);   // hi*lo
                MMA(acc[nt], al, bh0, bh1);   // lo*hi  (lo*lo dropped)
            }
        }
    }

    const int r0 = rowBase + w * 16 + (lane >> 2);
    const int colb = (lane & 3) * 2;
    #pragma unroll
    for (int nt = 0; nt < 16; ++nt) {
        if (r0 < N) {
            __half2 h = __floats2half2_rn(tanhf(acc[nt][0]), tanhf(acc[nt][1]));
            *(__half2*)(C + (size_t)r0 * 128 + nt * 8 + colb) = h;
        }
        if (r0 + 8 < N) {
            __half2 h = __floats2half2_rn(tanhf(acc[nt][2]), tanhf(acc[nt][3]));
            *(__half2*)(C + (size_t)(r0 + 8) * 128 + nt * 8 + colb) = h;
        }
    }
}

// --- tmp[N,pad64](half) = A[N,128](half, exact) @ W2 (split) via MMA.
// Manual LDS fragment loads (round-6 proven pattern). W2 tile load FIXED:
// 16 uint4 per 128-half row (was 8 with stride-16 holes -> NaN).
__global__ __launch_bounds__(256, 2) void gemm40_mma(const __half* __restrict__ A,
                                                     __half* __restrict__ out, int N) {
    __shared__ __half sA[128][KP];
    __shared__ __half sW2h[CDIM][KP2], sW2l[CDIM][KP2];
    const int tid = threadIdx.x;
    const int lane = tid & 31;
    const int w = tid >> 5;
    const int rowBase = blockIdx.x * 128;

    // W2T full-K tiles, loaded once: 40 rows x 128 halves = 16 uint4 per row
    for (int i = tid; i < CDIM * 16; i += 256) {
        int n = i >> 4, c = (i & 15) * 8;
        *(uint4*)&sW2h[n][c] = *(const uint4*)(g_W2T_hi + n * H + c);
        *(uint4*)&sW2l[n][c] = *(const uint4*)(g_W2T_lo + n * H + c);
    }

    float acc[5][4];
    #pragma unroll
    for (int t = 0; t < 5; ++t)
        #pragma unroll
        for (int j = 0; j < 4; ++j) acc[t][j] = 0.f;

    for (int kb = 0; kb < 128; kb += 32) {
        __syncthreads();
        // A slice: 128 rows x 32 halves (2 uint4 per thread)
        #pragma unroll
        for (int p = 0; p < 2; ++p) {
            int idx = p * 256 + tid;
            int r = idx >> 2, c = (idx & 3) * 8;
            int gr = rowBase + r;
            uint4 v = make_uint4(0u, 0u, 0u, 0u);
            if (gr < N) v = *(const uint4*)(A + (size_t)gr * H + kb + c);
            *(uint4*)&sA[r][c] = v;
        }
        __syncthreads();

        #pragma unroll
        for (int ks = 0; ks < 2; ++ks) {
            const int koff = ks * 16 + (lane & 3) * 2;   // within 32-k A tile
            const int kg   = kb + koff;                  // global k for W2 tile
            const int ra   = w * 16 + (lane >> 2);
            unsigned a[4];
            a[0] = *(const unsigned*)&sA[ra][koff];
            a[1] = *(const unsigned*)&sA[ra + 8][koff];
            a[2] = *(const unsigned*)&sA[ra][koff + 8];
            a[3] = *(const unsigned*)&sA[ra + 8][koff + 8];
            #pragma unroll
            for (int nt = 0; nt < 5; ++nt) {
                const int nb = nt * 8 + (lane >> 2);
                unsigned bh0 = *(const unsigned*)&sW2h[nb][kg];
                unsigned bh1 = *(const unsigned*)&sW2h[nb][kg + 8];
                unsigned bl0 = *(const unsigned*)&sW2l[nb][kg];
                unsigned bl1 = *(const unsigned*)&sW2l[nb][kg + 8];
                MMA(acc[nt], a, bh0, bh1);   // A exact fp16: 2 passes suffice
                MMA(acc[nt], a, bl0, bl1);
            }
        }
    }

    const int r0 = rowBase + w * 16 + (lane >> 2);
    const int colb = (lane & 3) * 2;
    #pragma unroll
    for (int nt = 0; nt < 5; ++nt) {   // cols nt*8+colb in [0,40)
        if (r0 < N) {
            __half2 h = __floats2half2_rn(acc[nt][0], acc[nt][1]);
            *(__half2*)(out + (size_t)r0 * TMPW + nt * 8 + colb) = h;
        }
        if (r0 + 8 < N) {
            __half2 h = __floats2half2_rn(acc[nt][2], acc[nt][3]);
            *(__half2*)(out + (size_t)(r0 + 8) * TMPW + nt * 8 + colb) = h;
        }
    }
}

extern "C" void kernel_launch(void* const* d_in, const int* in_sizes, int n_in,
                              void* d_out, int out_size) {
    const float* x    = (const float*)d_in[0];
    const int*   esrc = (const int*)d_in[1];
    const int*   edst = (const int*)d_in[2];
    const float* ew   = (const float*)d_in[3];
    const float* W0   = (const float*)d_in[4];
    const float* W1   = (const float*)d_in[5];
    const float* W2   = (const float*)d_in[6];
    float* out = (float*)d_out;

    const int N = in_sizes[0] / H;
    const int E = in_sizes[1];

    float* agg; __half *xh, *hb, *tmp; int* rp;
    __half *w0h, *w0l, *w1h, *w1l;
    cudaGetSymbolAddress((void**)&agg, g_agg);
    cudaGetSymbolAddress((void**)&xh,  g_xh);
    cudaGetSymbolAddress((void**)&hb,  g_hb);
    cudaGetSymbolAddress((void**)&tmp, g_tmp);
    cudaGetSymbolAddress((void**)&rp,  g_rowptr);
    cudaGetSymbolAddress((void**)&w0h, g_W0T_hi);
    cudaGetSymbolAddress((void**)&w0l, g_W0T_lo);
    cudaGetSymbolAddress((void**)&w1h, g_W1T_hi);
    cudaGetSymbolAddress((void**)&w1l, g_W1T_lo);

    const int gemmBlocks = (N + 127) / 128;
    const int spmmBlocks = (N + 7) / 8;

    const int n2h = N * H / 2;
    const int bF = (n2h + 255) / 256;
    const int bR = (N + 256) / 256;
    const int bW = (H * H + 255) / 256;
    const int bW2 = (H * CDIM + 255) / 256;
    prep_kernel<<<bF + bR + 2 * bW + bW2, 256>>>(x, n2h, bF, edst, E, N, bR,
                                                 W0, W1, W2, bW, xh, rp);

    // layer 1: h = tanh(spmm(x) @ W0)
    spmm_h128<<<spmmBlocks, 256>>>(xh, esrc, ew, rp, agg, N);
    gemm128_mma_tanh<<<gemmBlocks, 256>>>(agg, w0h, w0l, hb, N);

    // layer 2: h = tanh(spmm(h) @ W1)
    spmm_h128<<<spmmBlocks, 256>>>(hb, esrc, ew, rp, agg, N);
    gemm128_mma_tanh<<<gemmBlocks, 256>>>(agg, w1h, w1l, hb, N);

    // layer 3 (reassociated): out = tanh(spmm(h @ W2)) -- 40-wide fp16 gather
    gemm40_mma<<<gemmBlocks, 256>>>(hb, tmp, N);
    spmm_h40_tanh<<<spmmBlocks, 256>>>(tmp, esrc, ew, rp, out, N);
}